// round 12
// baseline (speedup 1.0000x reference)
#include <cuda_runtime.h>
#include <cuda_fp16.h>
#include <stdint.h>
#include <math.h>

#define Bn 8
#define Hn 8
#define Sn 1024
#define DMn 512
#define DKn 64
#define MROWS (Bn * 1024)   // 8192

// ---------------- scratch (device globals; no runtime allocation) ----------------
__device__ uint32_t g_xr[MROWS * 256], g_xf[MROWS * 256];      // inputs, single fp16
__device__ uint32_t g_W[8][DMn * 256];                         // weights, single fp16
__device__ uint32_t g_Qr[Bn*Hn*Sn*32], g_Qf[Bn*Hn*Sn*32];      // single fp16
__device__ uint32_t g_Kr[Bn*Hn*Sn*32], g_Kf[Bn*Hn*Sn*32];      // single fp16
__device__ uint32_t g_V[Bn*Hn*128*512];                        // single fp16 [bh][Vr d0-63|Vf d64-127][s-pairs]
__device__ uint32_t g_Crh[MROWS * 256], g_Crl[MROWS * 256];    // contexts split (output-critical)
__device__ uint32_t g_Cfh[MROWS * 256], g_Cfl[MROWS * 256];

#define SMEM1 33792     // 1-pass gemm kernels
#define SMEM2 49152     // 2-pass gemm kernels

__device__ __forceinline__ uint32_t smem_u32(const void* p) {
    uint32_t a;
    asm("{ .reg .u64 t; cvta.to.shared.u64 t, %1; cvt.u32.u64 %0, t; }" : "=r"(a) : "l"(p));
    return a;
}

#define CP_ASYNC16(dst, src) \
    asm volatile("cp.async.cg.shared.global [%0], [%1], 16;" :: "r"(dst), "l"(src))
#define CP_COMMIT() asm volatile("cp.async.commit_group;" ::: "memory")
#define CP_WAIT(n)  asm volatile("cp.async.wait_group %0;" :: "n"(n) : "memory")

__device__ __forceinline__ uint32_t hpair(float a, float b) {
    __half2 t = __floats2half2_rn(a, b);
    return *reinterpret_cast<uint32_t*>(&t);
}

// permuted offset within a row for even k, matching SMEM physical tile order
__device__ __forceinline__ size_t perm_off(size_t rowbase32, int k) {
    const int c = k >> 5, t = (k & 31) >> 1;
    const int g = ((t >> 3) << 1) | ((t >> 1) & 1);
    const int s = ((t & 1) << 1) | ((t >> 2) & 1);
    return rowbase32 + c * 16 + g * 4 + s;
}

__device__ __forceinline__ void single_pair_store(
    uint32_t* __restrict__ dst, size_t rowbase32, int k, float v0, float v1)
{
    dst[perm_off(rowbase32, k)] = hpair(v0, v1);
}

__device__ __forceinline__ void split_pair_store(
    uint32_t* __restrict__ hi, uint32_t* __restrict__ lo,
    size_t rowbase32, int k, float v0, float v1)
{
    const size_t off = perm_off(rowbase32, k);
    __half h0 = __float2half_rn(v0), h1 = __float2half_rn(v1);
    hi[off] = hpair(__half2float(h0), __half2float(h1));
    lo[off] = hpair(v0 - __half2float(h0), v1 - __half2float(h1));
}

// SMEM physical u32 index for direct p-tile writes (perm + cp.async row-xor swizzle
// composed; row stride = 32 u32 for a 64-col fp16 tile)
__device__ __forceinline__ int ptile_idx(int r, int k) {
    const int chunk = k >> 5, t = (k & 31) >> 1;
    const int gg = ((t >> 3) << 1) | ((t >> 1) & 1);
    const int ss = ((t & 1) << 1) | ((t >> 2) & 1);
    const int i  = gg * 4 + ss;
    return r * 32 + chunk * 16 + ((((i >> 2) * 4) ^ ((r & 2) << 2)) + (i & 3));
}

// ---------------- converters ----------------
__global__ void conv_x(const float* __restrict__ xr, const float* __restrict__ xf,
                       uint32_t* __restrict__ dr, uint32_t* __restrict__ df)
{
    const float* X = blockIdx.z ? xf : xr;
    uint32_t* D = blockIdx.z ? df : dr;
    const size_t i = (size_t)blockIdx.x * 256 + threadIdx.x;
    const size_t row = i >> 8;
    const int k = (int)(i & 255) * 2;
    float2 v = *reinterpret_cast<const float2*>(X + row * 512 + k);
    single_pair_store(D, row * 256, k, v.x, v.y);
}

struct Ptrs8 { const float* p[8]; };
__global__ void conv_w(Ptrs8 wp, uint32_t* __restrict__ Wd)
{
    const int z = blockIdx.z;
    const float* X = wp.p[z];
    uint32_t* D = Wd + (size_t)z * DMn * 256;
    const size_t i = (size_t)blockIdx.x * 256 + threadIdx.x;
    const size_t row = i >> 8;
    const int k = (int)(i & 255) * 2;
    float2 v = *reinterpret_cast<const float2*>(X + row * 512 + k);
    single_pair_store(D, row * 256, k, v.x, v.y);
}

#define MMA(c, a, b) \
    asm volatile( \
        "mma.sync.aligned.m16n8k16.row.col.f32.f16.f16.f32 " \
        "{%0,%1,%2,%3},{%4,%5,%6,%7},{%8,%9},{%0,%1,%2,%3};" \
        : "+f"((c)[0]), "+f"((c)[1]), "+f"((c)[2]), "+f"((c)[3]) \
        : "r"((a)[0]), "r"((a)[1]), "r"((a)[2]), "r"((a)[3]), \
          "r"((b)[0]), "r"((b)[1]))

// ---------------- shared GEMM mainloop (double-buffered cp.async) ----------------
template <int NPASS>
__device__ __forceinline__ void gemm_core(
    char* smem, uint32_t sb, int tid,
    const uint32_t* __restrict__ Ahi, const uint32_t* __restrict__ Alo,
    const uint32_t* __restrict__ Bs,
    size_t aRow0, size_t bRow0, int rowA32, int nc,
    float acc[4][4][4])
{
    constexpr int T_ALOo = 8192;
    constexpr int T_Bo   = (NPASS == 2) ? 16384 : 8192;
    constexpr int STAGEo = (NPASS == 2) ? 24576 : 16384;

    const int w = tid >> 5, lane = tid & 31;
    const int wm = w >> 2, wn = w & 3;
    const int g = lane >> 2, tig = lane & 3;
    const int prr = tid >> 2, pg = tid & 3;

    #pragma unroll
    for (int i = 0; i < 4; i++)
        #pragma unroll
        for (int j = 0; j < 4; j++)
            #pragma unroll
            for (int c = 0; c < 4; c++) acc[i][j][c] = 0.f;

    auto issue = [&](int cc, int st) {
        const uint32_t so = sb + st * STAGEo;
        #pragma unroll
        for (int it = 0; it < 2; it++) {
            const int r = prr + it * 64;
            const uint32_t sw = (uint32_t)(r * 64 + ((pg * 16) ^ ((r & 2) << 4)));
            const size_t srcA = aRow0 + (size_t)r * rowA32 + cc * 16 + pg * 4;
            const size_t srcB = bRow0 + (size_t)r * rowA32 + cc * 16 + pg * 4;
            CP_ASYNC16(so + sw, Ahi + srcA);
            if (NPASS == 2) CP_ASYNC16(so + T_ALOo + sw, Alo + srcA);
            CP_ASYNC16(so + T_Bo + sw, Bs + srcB);
        }
    };

    issue(0, 0);
    CP_COMMIT();

    for (int cc = 0; cc < nc; cc++) {
        if (cc + 1 < nc) { issue(cc + 1, (cc + 1) & 1); CP_COMMIT(); CP_WAIT(1); }
        else             { CP_WAIT(0); }
        __syncthreads();
        const char* sm = smem + (cc & 1) * STAGEo;

        #pragma unroll
        for (int s = 0; s < 2; s++) {
            uint32_t bfr[4][2], Af[4][4];
            #pragma unroll
            for (int j = 0; j < 4; j++) {
                const int rB = wn * 32 + j * 8 + g;
                const uint32_t co = (uint32_t)((s * 32 + tig * 8) ^ ((rB & 2) << 4)) + rB * 64;
                uint2 u = *reinterpret_cast<const uint2*>(sm + T_Bo + co);
                bfr[j][0] = u.x; bfr[j][1] = u.y;
            }
            #pragma unroll
            for (int i = 0; i < 4; i++) {
                const int r0 = wm * 64 + i * 16 + g;
                const uint32_t co = (uint32_t)((s * 32 + tig * 8) ^ ((r0 & 2) << 4));
                uint2 u = *reinterpret_cast<const uint2*>(sm + r0 * 64 + co);
                uint2 v = *reinterpret_cast<const uint2*>(sm + (r0 + 8) * 64 + co);
                Af[i][0] = u.x; Af[i][1] = v.x; Af[i][2] = u.y; Af[i][3] = v.y;
            }
            #pragma unroll
            for (int i = 0; i < 4; i++)
                #pragma unroll
                for (int j = 0; j < 4; j++) MMA(acc[i][j], Af[i], bfr[j]);
            if (NPASS == 2) {
                #pragma unroll
                for (int i = 0; i < 4; i++) {
                    const int r0 = wm * 64 + i * 16 + g;
                    const uint32_t co = (uint32_t)((s * 32 + tig * 8) ^ ((r0 & 2) << 4));
                    uint2 u = *reinterpret_cast<const uint2*>(sm + T_ALOo + r0 * 64 + co);
                    uint2 v = *reinterpret_cast<const uint2*>(sm + T_ALOo + (r0 + 8) * 64 + co);
                    Af[i][0] = u.x; Af[i][1] = v.x; Af[i][2] = u.y; Af[i][3] = v.y;
                }
                #pragma unroll
                for (int i = 0; i < 4; i++)
                    #pragma unroll
                    for (int j = 0; j < 4; j++) MMA(acc[i][j], Af[i], bfr[j]);
            }
        }
        __syncthreads();
    }
}

__device__ __forceinline__ void acc_to_sC(float* sC, float acc[4][4][4], int tid,
                                          int hh, float alpha, const float* bias, int bn)
{
    const int w = tid >> 5, lane = tid & 31;
    const int wm = w >> 2, wn = w & 3;
    const int g = lane >> 2, tig = lane & 3;
    if (wm == hh) {
        #pragma unroll
        for (int i = 0; i < 4; i++) {
            const int rl = i * 16 + g;
            #pragma unroll
            for (int j = 0; j < 4; j++) {
                const int cl = wn * 32 + j * 8 + 2 * tig;
                float bv0 = 0.f, bv1 = 0.f;
                if (bias) { bv0 = __ldg(bias + bn + cl); bv1 = __ldg(bias + bn + cl + 1); }
                float2 v0 = make_float2(acc[i][j][0] * alpha + bv0,
                                        acc[i][j][1] * alpha + bv1);
                float2 v1 = make_float2(acc[i][j][2] * alpha + bv0,
                                        acc[i][j][3] * alpha + bv1);
                *reinterpret_cast<float2*>(&sC[rl * 132 + cl]) = v0;
                *reinterpret_cast<float2*>(&sC[(rl + 8) * 132 + cl]) = v1;
            }
        }
    }
}

// ---------------- fused 6-projection kernel (1-pass A) ----------------
struct ProjArgs {
    const uint32_t *xr, *xf, *Wd;
    const float* bias[6];
    uint32_t *Qr, *Kr, *Qf, *Kf, *V;
};

__global__ void __launch_bounds__(256, 2) proj_kernel(ProjArgs pa)
{
    extern __shared__ char smem[];
    const uint32_t sb = smem_u32(smem);
    const int tid = threadIdx.x;
    const int z = blockIdx.z;
    const int bm = blockIdx.y * 128, bn = blockIdx.x * 128;

    const uint32_t* A = (z < 3) ? pa.xr : pa.xf;
    const uint32_t* Bw = pa.Wd + (size_t)z * DMn * 256;

    float acc[4][4][4];
    gemm_core<1>(smem, sb, tid, A, nullptr, Bw,
                 (size_t)bm * 256, (size_t)bn * 256, 256, 16, acc);

    float* sC = reinterpret_cast<float*>(smem);
    const int mode = z % 3;
    uint32_t* dst = (mode == 0) ? (z < 3 ? pa.Qr : pa.Qf)
                  : (mode == 1) ? (z < 3 ? pa.Kr : pa.Kf) : pa.V;
    const int vhalf = (z >= 3) ? 1 : 0;

    #pragma unroll
    for (int hh = 0; hh < 2; hh++) {
        acc_to_sC(sC, acc, tid, hh, 1.f, pa.bias[z], bn);
        __syncthreads();
        const int mbase = bm + hh * 64;
        const int b = mbase >> 10, h0 = bn >> 6;
        if (mode < 2) {
            const int s0 = mbase & 1023;
            for (int e = tid; e < 64 * 64; e += 256) {
                const int rl = e >> 6, p = e & 63, col = p * 2;
                const int hd = col >> 6, d = col & 63;
                const size_t rowIdx = ((size_t)(b * Hn + h0 + hd)) * Sn + s0 + rl;
                single_pair_store(dst, rowIdx * 32, d,
                                  sC[rl * 132 + col], sC[rl * 132 + col + 1]);
            }
        } else {
            const int sLoc = mbase & 1023;
            for (int e = tid; e < 32 * 128; e += 256) {
                const int col = e & 127, sl = (e >> 7) * 2;
                const int hd = col >> 6, d = col & 63;
                const size_t vrow = ((size_t)(b * Hn + h0 + hd)) * 128 + vhalf * 64 + d;
                single_pair_store(dst, vrow * 512, sLoc + sl,
                                  sC[sl * 132 + col], sC[(sl + 1) * 132 + col]);
            }
        }
        __syncthreads();
    }
}

// ---------------- fast exp ----------------
__device__ __forceinline__ float fexp(float x) {
    float t  = x * 1.4426950408889634f;
    float fi = rintf(t);
    float f  = t - fi;
    float p  = 1.3333558146428443e-3f;
    p = fmaf(p, f, 9.6181291076284770e-3f);
    p = fmaf(p, f, 5.5504108664821580e-2f);
    p = fmaf(p, f, 2.4022650695910072e-1f);
    p = fmaf(p, f, 6.9314718055994531e-1f);
    p = fmaf(p, f, 1.0f);
    int e = (int)fi;
    return __int_as_float(__float_as_int(p) + (e << 23));
}
__device__ __forceinline__ float fexp_s(float x) { return fexp(fmaxf(x, -80.f)); }

// ================= fused attention: score + softmax + max-merge + PV =================
// CTA: 64 q-rows x full S (two passes over 16 k-tiles of 64). grid (16, 64)
#define QT 64
#define KTILE 64
#define NKT 16
#define FA_QR 0
#define FA_QF 8192
#define FA_P  16384
#define FA_SCR 24576
#define FA_ST 28672
#define FA_STAGE 32768
#define FA_V_OFF 16384
#define FA_SMEM (FA_ST + 2 * FA_STAGE)   // 94208

__global__ void __launch_bounds__(256, 2) fa_kernel(
    const uint32_t* __restrict__ Qr, const uint32_t* __restrict__ Kr,
    const uint32_t* __restrict__ Qf, const uint32_t* __restrict__ Kf,
    const uint32_t* __restrict__ Vc,
    uint32_t* __restrict__ Crh, uint32_t* __restrict__ Crl,
    uint32_t* __restrict__ Cfh, uint32_t* __restrict__ Cfl)
{
    extern __shared__ char smem[];
    const uint32_t sb = smem_u32(smem);
    const int tid = threadIdx.x;
    const int w = tid >> 5, lane = tid & 31;
    const int wm = w >> 2, wn = w & 3;
    const int g = lane >> 2, tig = lane & 3;
    const int qt = blockIdx.x, bh = blockIdx.y;
    const int qbase = qt * QT;

    auto issueK = [&](int kt, int stg) {
        const uint32_t so = sb + FA_ST + stg * FA_STAGE;
        #pragma unroll
        for (int i = 0; i < 4; i++) {
            const int e = tid + (i << 8);
            const int tile = e >> 9, e2 = e & 511;
            const int r = e2 >> 3, q = e2 & 7;
            const int chunk = q >> 2, pg = q & 3;
            const uint32_t* src = (tile ? Kf : Kr)
                + ((size_t)bh * Sn + kt * KTILE + r) * 32 + chunk * 16 + pg * 4;
            CP_ASYNC16(so + tile * 8192 + r * 128 + chunk * 64
                       + (uint32_t)((pg * 16) ^ ((r & 2) << 4)), src);
        }
    };
    auto issueV = [&](int kt, int stg) {
        const uint32_t so = sb + FA_ST + stg * FA_STAGE + FA_V_OFF;
        #pragma unroll
        for (int i = 0; i < 4; i++) {
            const int e = tid + (i << 8);
            const int r = e >> 3, q = e & 7;
            const int chunk = q >> 2, pg = q & 3;
            const uint32_t* src = Vc + ((size_t)bh * 128 + r) * 512
                + (kt * 2 + chunk) * 16 + pg * 4;
            CP_ASYNC16(so + r * 128 + chunk * 64
                       + (uint32_t)((pg * 16) ^ ((r & 2) << 4)), src);
        }
    };

    // S-tile MMA: A = Q tile (64 q x 64 d), B = K tile (64 s x 64 d)
    auto smma = [&](int qoff, uint32_t koff, float acc[2][2][4]) {
        #pragma unroll
        for (int k4 = 0; k4 < 4; k4++) {
            const int chunk = k4 >> 1, s = k4 & 1;
            uint32_t Af[2][4], Bf[2][2];
            #pragma unroll
            for (int mt = 0; mt < 2; mt++) {
                const int r0 = wm * 32 + mt * 16 + g;
                const uint32_t co = (uint32_t)((s * 32 + tig * 8) ^ ((r0 & 2) << 4)) + chunk * 64;
                uint2 u = *reinterpret_cast<const uint2*>(smem + qoff + r0 * 128 + co);
                uint2 v = *reinterpret_cast<const uint2*>(smem + qoff + (r0 + 8) * 128 + co);
                Af[mt][0] = u.x; Af[mt][1] = v.x; Af[mt][2] = u.y; Af[mt][3] = v.y;
            }
            #pragma unroll
            for (int j = 0; j < 2; j++) {
                const int rB = wn * 16 + j * 8 + g;
                const uint32_t co = (uint32_t)((s * 32 + tig * 8) ^ ((rB & 2) << 4)) + chunk * 64;
                uint2 u = *reinterpret_cast<const uint2*>(smem + koff + rB * 128 + co);
                Bf[j][0] = u.x; Bf[j][1] = u.y;
            }
            #pragma unroll
            for (int mt = 0; mt < 2; mt++)
                #pragma unroll
                for (int j = 0; j < 2; j++) MMA(acc[mt][j], Af[mt], Bf[j]);
        }
    };

    // ---- Q load (group 0 with first K issue) ----
    #pragma unroll
    for (int i = 0; i < 4; i++) {
        const int e = tid + (i << 8);
        const int st = e >> 9, e2 = e & 511;
        const int r = e2 >> 3, q = e2 & 7;
        const int chunk = q >> 2, pg = q & 3;
        const uint32_t* src = (st ? Qf : Qr)
            + ((size_t)bh * Sn + qbase + r) * 32 + chunk * 16 + pg * 4;
        CP_ASYNC16(sb + (st ? FA_QF : FA_QR) + r * 128 + chunk * 64
                   + (uint32_t)((pg * 16) ^ ((r & 2) << 4)), src);
    }

    // ================= pass A: online (m, Z) per row per stream =================
    float mS[2][4], zS[2][4];
    #pragma unroll
    for (int s2 = 0; s2 < 2; s2++)
        #pragma unroll
        for (int i = 0; i < 4; i++) { mS[s2][i] = -1e30f; zS[s2][i] = 0.f; }

    issueK(0, 0);
    CP_COMMIT();
    for (int kt = 0; kt < NKT; kt++) {
        if (kt + 1 < NKT) { issueK(kt + 1, (kt + 1) & 1); CP_COMMIT(); CP_WAIT(1); }
        else             { CP_WAIT(0); }
        __syncthreads();
        const uint32_t stO = FA_ST + (uint32_t)(kt & 1) * FA_STAGE;
        float accR[2][2][4], accF[2][2][4];
        #pragma unroll
        for (int a = 0; a < 2; a++)
            #pragma unroll
            for (int b2 = 0; b2 < 2; b2++)
                #pragma unroll
                for (int c = 0; c < 4; c++) { accR[a][b2][c] = 0.f; accF[a][b2][c] = 0.f; }
        smma(FA_QR, stO, accR);
        smma(FA_QF, stO + 8192, accF);
        #pragma unroll
        for (int s2 = 0; s2 < 2; s2++) {
            float (*A)[2][4] = s2 ? accF : accR;
            #pragma unroll
            for (int mt = 0; mt < 2; mt++)
                #pragma unroll
                for (int h = 0; h < 2; h++) {
                    const int rs = mt * 2 + h;
                    const float v0 = A[mt][0][h*2] * 0.125f, v1 = A[mt][0][h*2+1] * 0.125f;
                    const float v2 = A[mt][1][h*2] * 0.125f, v3 = A[mt][1][h*2+1] * 0.125f;
                    const float tmax = fmaxf(fmaxf(v0, v1), fmaxf(v2, v3));
                    const float mn = fmaxf(mS[s2][rs], tmax);
                    zS[s2][rs] = zS[s2][rs] * fexp_s(mS[s2][rs] - mn)
                               + fexp_s(v0 - mn) + fexp_s(v1 - mn)
                               + fexp_s(v2 - mn) + fexp_s(v3 - mn);
                    mS[s2][rs] = mn;
                }
        }
        __syncthreads();
    }

    // ---- merge: intra-quad (tig), then cross-wn via SMEM scratch ----
    #pragma unroll
    for (int s2 = 0; s2 < 2; s2++)
        #pragma unroll
        for (int rs = 0; rs < 4; rs++) {
            float m = mS[s2][rs], z = zS[s2][rs];
            #pragma unroll
            for (int off = 1; off < 4; off <<= 1) {
                const float om = __shfl_xor_sync(0xffffffffu, m, off);
                const float oz = __shfl_xor_sync(0xffffffffu, z, off);
                const float mn = fmaxf(m, om);
                z = z * fexp_s(m - mn) + oz * fexp_s(om - mn);
                m = mn;
            }
            mS[s2][rs] = m; zS[s2][rs] = z;
        }
    float* scr = reinterpret_cast<float*>(smem + FA_SCR);
    if (tig == 0) {
        #pragma unroll
        for (int s2 = 0; s2 < 2; s2++)
            #pragma unroll
            for (int rs = 0; rs < 4; rs++) {
                const int row = wm * 32 + (rs >> 1) * 16 + (rs & 1) * 8 + g;
                scr[((s2 * 64 + row) * 4 + wn) * 2]     = mS[s2][rs];
                scr[((s2 * 64 + row) * 4 + wn) * 2 + 1] = zS[s2][rs];
            }
    }
    __syncthreads();
    float mF[2][4], iZ[2][4];
    #pragma unroll
    for (int s2 = 0; s2 < 2; s2++)
        #pragma unroll
        for (int rs = 0; rs < 4; rs++) {
            const int row = wm * 32 + (rs >> 1) * 16 + (rs & 1) * 8 + g;
            float m = -1e30f;
            #pragma unroll
            for (int ww = 0; ww < 4; ww++)
                m = fmaxf(m, scr[((s2 * 64 + row) * 4 + ww) * 2]);
            float Z = 0.f;
            #pragma unroll
            for (int ww = 0; ww < 4; ww++)
                Z += scr[((s2 * 64 + row) * 4 + ww) * 2 + 1]
                   * fexp_s(scr[((s2 * 64 + row) * 4 + ww) * 2] - m);
            mF[s2][rs] = m; iZ[s2][rs] = 1.f / Z;
        }

    // ================= pass B: recompute S, p = max-merge, PV MMA =================
    float accPV[2][4][4];
    #pragma unroll
    for (int a = 0; a < 2; a++)
        #pragma unroll
        for (int b2 = 0; b2 < 4; b2++)
            #pragma unroll
            for (int c = 0; c < 4; c++) accPV[a][b2][c] = 0.f;

    issueK(0, 0); issueV(0, 0);
    CP_COMMIT();
    uint32_t* pP = reinterpret_cast<uint32_t*>(smem + FA_P);
    for (int kt = 0; kt < NKT; kt++) {
        if (kt + 1 < NKT) {
            issueK(kt + 1, (kt + 1) & 1); issueV(kt + 1, (kt + 1) & 1);
            CP_COMMIT(); CP_WAIT(1);
        } else CP_WAIT(0);
        __syncthreads();
        const uint32_t stO = FA_ST + (uint32_t)(kt & 1) * FA_STAGE;
        float accR[2][2][4], accF[2][2][4];
        #pragma unroll
        for (int a = 0; a < 2; a++)
            #pragma unroll
            for (int b2 = 0; b2 < 2; b2++)
                #pragma unroll
                for (int c = 0; c < 4; c++) { accR[a][b2][c] = 0.f; accF[a][b2][c] = 0.f; }
        smma(FA_QR, stO, accR);
        smma(FA_QF, stO + 8192, accF);

        #pragma unroll
        for (int mt = 0; mt < 2; mt++)
            #pragma unroll
            for (int j = 0; j < 2; j++)
                #pragma unroll
                for (int h = 0; h < 2; h++) {
                    const int rs = mt * 2 + h;
                    const int row = wm * 32 + mt * 16 + h * 8 + g;
                    const float vr0 = accR[mt][j][h*2] * 0.125f, vr1 = accR[mt][j][h*2+1] * 0.125f;
                    const float vf0 = accF[mt][j][h*2] * 0.125f, vf1 = accF[mt][j][h*2+1] * 0.125f;
                    const float p0 = fmaxf(fexp_s(vr0 - mF[0][rs]) * iZ[0][rs],
                                           fexp_s(vf0 - mF[1][rs]) * iZ[1][rs]);
                    const float p1 = fmaxf(fexp_s(vr1 - mF[0][rs]) * iZ[0][rs],
                                           fexp_s(vf1 - mF[1][rs]) * iZ[1][rs]);
                    const int k = wn * 16 + j * 8 + 2 * tig;
                    pP[ptile_idx(row, k)] = hpair(p0, p1);
                }
        __syncthreads();

        // PV MMA: A = p tile (64 q x 64 s), B = V tile (128 d x 64 s)
        #pragma unroll
        for (int k4 = 0; k4 < 4; k4++) {
            const int chunk = k4 >> 1, s = k4 & 1;
            uint32_t Af[2][4];
            #pragma unroll
            for (int mt = 0; mt < 2; mt++) {
                const int r0 = wm * 32 + mt * 16 + g;
                const uint32_t co = (uint32_t)((s * 32 + tig * 8) ^ ((r0 & 2) << 4)) + chunk * 64;
                uint2 u = *reinterpret_cast<const uint2*>(smem + FA_P + r0 * 128 + co);
                uint2 v = *reinterpret_cast<const uint2*>(smem + FA_P + (r0 + 8) * 128 + co);
                Af[mt][0] = u.x; Af[mt][1] = v.x; Af[mt][2] = u.y; Af[mt][3] = v.y;
            }
            #pragma unroll
            for (int j = 0; j < 4; j++) {
                const int rB = wn * 32 + j * 8 + g;
                const uint32_t co = (uint32_t)((s * 32 + tig * 8) ^ ((rB & 2) << 4)) + chunk * 64;
                uint2 u = *reinterpret_cast<const uint2*>(smem + stO + FA_V_OFF + rB * 128 + co);
                uint32_t Bf[2] = {u.x, u.y};
                #pragma unroll
                for (int mt = 0; mt < 2; mt++) MMA(accPV[mt][j], Af[mt], Bf);
            }
        }
        __syncthreads();
    }

    // ---- epilogue: accPV -> sC -> split hi/lo contexts ----
    float* sC = reinterpret_cast<float*>(smem + FA_ST);
    #pragma unroll
    for (int mt = 0; mt < 2; mt++) {
        const int rl = wm * 32 + mt * 16 + g;
        #pragma unroll
        for (int j = 0; j < 4; j++) {
            const int cl = wn * 32 + j * 8 + 2 * tig;
            sC[rl * 132 + cl]           = accPV[mt][j][0];
            sC[rl * 132 + cl + 1]       = accPV[mt][j][1];
            sC[(rl + 8) * 132 + cl]     = accPV[mt][j][2];
            sC[(rl + 8) * 132 + cl + 1] = accPV[mt][j][3];
        }
    }
    __syncthreads();
    const int b = bh >> 3, hh = bh & 7;
    for (int e = tid; e < 64 * 64; e += 256) {
        const int rl = e >> 6, p = e & 63;
        const int str = p >> 5, d = (p & 31) * 2;
        const int col = str * 64 + d;
        const size_t rowIdx = (size_t)b * Sn + qbase + rl;
        split_pair_store(str ? Cfh : Crh, str ? Cfl : Crl, rowIdx * 256, hh * 64 + d,
                         sC[rl * 132 + col], sC[rl * 132 + col + 1]);
    }
}

// ---------------- fused output projections (2-pass A) ----------------
__global__ void __launch_bounds__(256, 2) outproj_kernel(
    const uint32_t* __restrict__ Crh, const uint32_t* __restrict__ Crl,
    const uint32_t* __restrict__ Cfh, const uint32_t* __restrict__ Cfl,
    const uint32_t* __restrict__ Wd, const float* __restrict__ b6,
    const float* __restrict__ b7, float* __restrict__ out)
{
    extern __shared__ char smem[];
    const uint32_t sb = smem_u32(smem);
    const int tid = threadIdx.x;
    const int z = blockIdx.z;
    const int bm = blockIdx.y * 128, bn = blockIdx.x * 128;

    const uint32_t* Ahi = z ? Cfh : Crh;
    const uint32_t* Alo = z ? Cfl : Crl;
    const uint32_t* Bw = Wd + (size_t)(6 + z) * DMn * 256;
    const float* bias = z ? b7 : b6;
    float* C = out + (size_t)z * MROWS * DMn;

    float acc[4][4][4];
    gemm_core<2>(smem, sb, tid, Ahi, Alo, Bw,
                 (size_t)bm * 256, (size_t)bn * 256, 256, 16, acc);

    float* sC = reinterpret_cast<float*>(smem);
    #pragma unroll
    for (int hh = 0; hh < 2; hh++) {
        acc_to_sC(sC, acc, tid, hh, 1.f, bias, bn);
        __syncthreads();
        const int mbase = bm + hh * 64;
        for (int e = tid * 4; e < 64 * 128; e += 1024) {
            const int row = e >> 7, col = e & 127;
            float4 v = make_float4(sC[row * 132 + col],     sC[row * 132 + col + 1],
                                   sC[row * 132 + col + 2], sC[row * 132 + col + 3]);
            *reinterpret_cast<float4*>(&C[(size_t)(mbase + row) * DMn + bn + col]) = v;
        }
        __syncthreads();
    }
}

// ---------------- host ----------------
extern "C" void kernel_launch(void* const* d_in, const int* in_sizes, int n_in,
                              void* d_out, int out_size)
{
    const float* x_rgb  = (const float*)d_in[0];
    const float* x_flow = (const float*)d_in[1];
    Ptrs8 wp; const float* bW[8];
    for (int i = 0; i < 8; i++) { wp.p[i] = (const float*)d_in[2 + 2*i]; bW[i] = (const float*)d_in[3 + 2*i]; }
    float* out = (float*)d_out;

    uint32_t *xr,*xf,*Wd,*Qr,*Qf,*Kr,*Kf,*V,*Crh,*Crl,*Cfh,*Cfl;
    cudaGetSymbolAddress((void**)&xr, g_xr);   cudaGetSymbolAddress((void**)&xf, g_xf);
    cudaGetSymbolAddress((void**)&Wd, g_W);
    cudaGetSymbolAddress((void**)&Qr, g_Qr);   cudaGetSymbolAddress((void**)&Qf, g_Qf);
    cudaGetSymbolAddress((void**)&Kr, g_Kr);   cudaGetSymbolAddress((void**)&Kf, g_Kf);
    cudaGetSymbolAddress((void**)&V, g_V);
    cudaGetSymbolAddress((void**)&Crh, g_Crh); cudaGetSymbolAddress((void**)&Crl, g_Crl);
    cudaGetSymbolAddress((void**)&Cfh, g_Cfh); cudaGetSymbolAddress((void**)&Cfl, g_Cfl);

    cudaFuncSetAttribute((const void*)proj_kernel,    cudaFuncAttributeMaxDynamicSharedMemorySize, SMEM1);
    cudaFuncSetAttribute((const void*)fa_kernel,      cudaFuncAttributeMaxDynamicSharedMemorySize, FA_SMEM);
    cudaFuncSetAttribute((const void*)outproj_kernel, cudaFuncAttributeMaxDynamicSharedMemorySize, SMEM2);

    // 0) conversions
    conv_x<<<dim3(MROWS, 1, 2), 256>>>(x_rgb, x_flow, xr, xf);
    conv_w<<<dim3(DMn, 1, 8), 256>>>(wp, Wd);

    // 1) all six projections
    ProjArgs pa;
    pa.xr = xr; pa.xf = xf; pa.Wd = Wd;
    for (int i = 0; i < 6; i++) pa.bias[i] = bW[i];
    pa.Qr = Qr; pa.Kr = Kr; pa.Qf = Qf; pa.Kf = Kf; pa.V = V;
    proj_kernel<<<dim3(DMn / 128, MROWS / 128, 6), 256, SMEM1>>>(pa);

    // 2) fused attention (score + softmax + max-merge + PV)
    fa_kernel<<<dim3(Sn / QT, Bn * Hn), 256, FA_SMEM>>>(
        Qr, Kr, Qf, Kf, V, Crh, Crl, Cfh, Cfl);

    // 3) output projections
    outproj_kernel<<<dim3(DMn / 128, MROWS / 128, 2), 256, SMEM2>>>(
        Crh, Crl, Cfh, Cfl, Wd, bW[6], bW[7], out);
}

// round 16
// speedup vs baseline: 1.0070x; 1.0070x over previous
#include <cuda_runtime.h>
#include <cuda_fp16.h>
#include <stdint.h>
#include <math.h>

#define Bn 8
#define Hn 8
#define Sn 1024
#define DMn 512
#define DKn 64
#define MROWS (Bn * 1024)   // 8192

// ---------------- scratch (device globals; plain row-major fp16, u32 = 2 halves) ----------------
__device__ uint32_t g_xr[MROWS * 256], g_xf[MROWS * 256];      // [8192][512] halves
__device__ uint32_t g_W[8][DMn * 256];                         // [512][512] halves
__device__ uint32_t g_Qr[Bn*Hn*Sn*32], g_Qf[Bn*Hn*Sn*32];      // [bh][1024][64]
__device__ uint32_t g_Kr[Bn*Hn*Sn*32], g_Kf[Bn*Hn*Sn*32];
__device__ uint32_t g_V[Bn*Hn*128*512];                        // [bh][Vr d0-63|Vf d64-127][1024 s]
__device__ uint32_t g_Shr[(size_t)Bn*Hn*Sn*512];               // fp16 scores, plain
__device__ uint32_t g_Shf[(size_t)Bn*Hn*Sn*512];
__device__ uint32_t g_Ph[(size_t)Bn*Hn*Sn*512];                // merged P fp16, plain
__device__ uint32_t g_Crh[MROWS * 256], g_Crl[MROWS * 256];    // contexts split hi/lo
__device__ uint32_t g_Cfh[MROWS * 256], g_Cfl[MROWS * 256];

#define SMEM1 65536     // 1-pass: 2 stages x (A 16K + B 16K)
#define SMEM2 98304     // 2-pass: 2 stages x (A 16K + Alo 16K + B 16K)

__device__ __forceinline__ uint32_t smem_u32(const void* p) {
    uint32_t a;
    asm("{ .reg .u64 t; cvta.to.shared.u64 t, %1; cvt.u32.u64 %0, t; }" : "=r"(a) : "l"(p));
    return a;
}

#define CP_ASYNC16(dst, src) \
    asm volatile("cp.async.cg.shared.global [%0], [%1], 16;" :: "r"(dst), "l"(src))
#define CP_COMMIT() asm volatile("cp.async.commit_group;" ::: "memory")
#define CP_WAIT(n)  asm volatile("cp.async.wait_group %0;" :: "n"(n) : "memory")

__device__ __forceinline__ void ldsm4(uint32_t* r, uint32_t addr) {
    asm volatile("ldmatrix.sync.aligned.m8n8.x4.shared.b16 {%0,%1,%2,%3}, [%4];"
                 : "=r"(r[0]), "=r"(r[1]), "=r"(r[2]), "=r"(r[3]) : "r"(addr));
}

__device__ __forceinline__ uint32_t hpair(float a, float b) {
    __half2 t = __floats2half2_rn(a, b);
    return *reinterpret_cast<uint32_t*>(&t);
}
__device__ __forceinline__ uint32_t hpairh(__half a, __half b) {
    __half2 t = __halves2half2(a, b);
    return *reinterpret_cast<uint32_t*>(&t);
}

// plain split store: hi gets rounded fp16, lo the fp16 residual
__device__ __forceinline__ void split_store_plain(
    uint32_t* __restrict__ hi, uint32_t* __restrict__ lo,
    size_t idx, float v0, float v1)
{
    __half h0 = __float2half_rn(v0), h1 = __float2half_rn(v1);
    hi[idx] = hpairh(h0, h1);
    lo[idx] = hpair(v0 - __half2float(h0), v1 - __half2float(h1));
}

// ---------------- converters (plain fp16 cast, coalesced) ----------------
__global__ void conv_x(const float* __restrict__ xr, const float* __restrict__ xf,
                       uint32_t* __restrict__ dr, uint32_t* __restrict__ df)
{
    const float* X = blockIdx.z ? xf : xr;
    uint32_t* D = blockIdx.z ? df : dr;
    const size_t i = (size_t)blockIdx.x * 256 + threadIdx.x;   // pair index
    float2 v = *reinterpret_cast<const float2*>(X + i * 2);
    D[i] = hpair(v.x, v.y);
}

struct Ptrs8 { const float* p[8]; };
__global__ void conv_w(Ptrs8 wp, uint32_t* __restrict__ Wd)
{
    const int z = blockIdx.z;
    const float* X = wp.p[z];
    uint32_t* D = Wd + (size_t)z * DMn * 256;
    const size_t i = (size_t)blockIdx.x * 256 + threadIdx.x;
    float2 v = *reinterpret_cast<const float2*>(X + i * 2);
    D[i] = hpair(v.x, v.y);
}

#define MMA(c, a, b) \
    asm volatile( \
        "mma.sync.aligned.m16n8k16.row.col.f32.f16.f16.f32 " \
        "{%0,%1,%2,%3},{%4,%5,%6,%7},{%8,%9},{%0,%1,%2,%3};" \
        : "+f"((c)[0]), "+f"((c)[1]), "+f"((c)[2]), "+f"((c)[3]) \
        : "r"((a)[0]), "r"((a)[1]), "r"((a)[2]), "r"((a)[3]), \
          "r"((b)[0]), "r"((b)[1]))

// ---------------- shared GEMM mainloop: plain tiles + SW128 + ldmatrix ----------------
// Tiles: 128 rows x 64 halves (128B rows, one SW128 atom per row).
// Physical: row r, 16B-unit u stored at unit (u ^ (r&7)). k-chunk = 64 halves.
template <int NPASS>
__device__ __forceinline__ void gemm_core(
    uint32_t sb, int tid,
    const uint32_t* __restrict__ Ahi, const uint32_t* __restrict__ Alo,
    const uint32_t* __restrict__ Bs,
    size_t aRow0, size_t bRow0, int rowU, int nc,
    float acc[4][4][4])
{
    constexpr uint32_t T_ALO = 16384;
    constexpr uint32_t T_B   = (NPASS == 2) ? 32768u : 16384u;
    constexpr uint32_t STAGE = (NPASS == 2) ? 49152u : 32768u;

    const int w = tid >> 5, lane = tid & 31;
    const int wm = w >> 2, wn = w & 3;
    // ldmatrix lane mapping: matid selects 8x8 quadrant
    const int matid = lane >> 3, rIn = lane & 7;
    const int rowOff = ((matid & 1) << 3) + rIn;
    const int kOff8 = matid >> 1;              // 0 = k-lo 8 cols, 1 = k-hi
    // producer: 2 threads per row, 4x16B each
    const int prr = tid >> 1, pu = (tid & 1) * 4;

    #pragma unroll
    for (int i = 0; i < 4; i++)
        #pragma unroll
        for (int j = 0; j < 4; j++)
            #pragma unroll
            for (int c = 0; c < 4; c++) acc[i][j][c] = 0.f;

    auto issue = [&](int cc, int st) {
        const uint32_t so = sb + st * STAGE;
        const size_t srcA = aRow0 + (size_t)prr * rowU + cc * 32;
        const size_t srcB = bRow0 + (size_t)prr * rowU + cc * 32;
        #pragma unroll
        for (int j = 0; j < 4; j++) {
            const int u = pu + j;
            const uint32_t d = (uint32_t)(prr * 128 + (u ^ (prr & 7)) * 16);
            CP_ASYNC16(so + d, Ahi + srcA + u * 4);
            if (NPASS == 2) CP_ASYNC16(so + T_ALO + d, Alo + srcA + u * 4);
            CP_ASYNC16(so + T_B + d, Bs + srcB + u * 4);
        }
    };

    issue(0, 0);
    CP_COMMIT();

    for (int cc = 0; cc < nc; cc++) {
        if (cc + 1 < nc) { issue(cc + 1, (cc + 1) & 1); CP_COMMIT(); CP_WAIT(1); }
        else             { CP_WAIT(0); }
        __syncthreads();
        const uint32_t so = sb + (uint32_t)(cc & 1) * STAGE;

        #pragma unroll
        for (int s = 0; s < 4; s++) {
            const uint32_t ku = (uint32_t)(((s * 2 + kOff8) ^ rIn) * 16);
            uint32_t Bf[2][4];
            #pragma unroll
            for (int j = 0; j < 2; j++)
                ldsm4(Bf[j], so + T_B + (uint32_t)((wn * 32 + j * 16 + rowOff) * 128) + ku);
            #pragma unroll
            for (int i = 0; i < 4; i++) {
                uint32_t Af[4];
                ldsm4(Af, so + (uint32_t)((wm * 64 + i * 16 + rowOff) * 128) + ku);
                #pragma unroll
                for (int jb = 0; jb < 4; jb++) {
                    uint32_t b[2] = {Bf[jb >> 1][jb & 1], Bf[jb >> 1][(jb & 1) + 2]};
                    MMA(acc[i][jb], Af, b);
                }
            }
            if (NPASS == 2) {
                #pragma unroll
                for (int i = 0; i < 4; i++) {
                    uint32_t Af[4];
                    ldsm4(Af, so + T_ALO + (uint32_t)((wm * 64 + i * 16 + rowOff) * 128) + ku);
                    #pragma unroll
                    for (int jb = 0; jb < 4; jb++) {
                        uint32_t b[2] = {Bf[jb >> 1][jb & 1], Bf[jb >> 1][(jb & 1) + 2]};
                        MMA(acc[i][jb], Af, b);
                    }
                }
            }
        }
        __syncthreads();
    }
}

// stage this warp-group's half of acc into sC [64][132]
__device__ __forceinline__ void acc_to_sC(float* sC, float acc[4][4][4], int tid,
                                          int hh, float alpha, const float* bias, int bn)
{
    const int w = tid >> 5, lane = tid & 31;
    const int wm = w >> 2, wn = w & 3;
    const int g = lane >> 2, tig = lane & 3;
    if (wm == hh) {
        #pragma unroll
        for (int i = 0; i < 4; i++) {
            const int rl = i * 16 + g;
            #pragma unroll
            for (int j = 0; j < 4; j++) {
                const int cl = wn * 32 + j * 8 + 2 * tig;
                float bv0 = 0.f, bv1 = 0.f;
                if (bias) { bv0 = __ldg(bias + bn + cl); bv1 = __ldg(bias + bn + cl + 1); }
                float2 v0 = make_float2(acc[i][j][0] * alpha + bv0,
                                        acc[i][j][1] * alpha + bv1);
                float2 v1 = make_float2(acc[i][j][2] * alpha + bv0,
                                        acc[i][j][3] * alpha + bv1);
                *reinterpret_cast<float2*>(&sC[rl * 132 + cl]) = v0;
                *reinterpret_cast<float2*>(&sC[(rl + 8) * 132 + cl]) = v1;
            }
        }
    }
}

// ---------------- fused 6-projection kernel (1-pass) ----------------
struct ProjArgs {
    const uint32_t *xr, *xf, *Wd;
    const float* bias[6];
    uint32_t *Qr, *Kr, *Qf, *Kf, *V;
};

__global__ void __launch_bounds__(256, 2) proj_kernel(ProjArgs pa)
{
    extern __shared__ char smem[];
    const uint32_t sb = smem_u32(smem);
    const int tid = threadIdx.x;
    const int z = blockIdx.z;
    const int bm = blockIdx.y * 128, bn = blockIdx.x * 128;

    const uint32_t* A = (z < 3) ? pa.xr : pa.xf;
    const uint32_t* Bw = pa.Wd + (size_t)z * DMn * 256;

    float acc[4][4][4];
    gemm_core<1>(sb, tid, A, nullptr, Bw,
                 (size_t)bm * 256, (size_t)bn * 256, 256, 8, acc);

    float* sC = reinterpret_cast<float*>(smem);
    const int mode = z % 3;
    uint32_t* dst = (mode == 0) ? (z < 3 ? pa.Qr : pa.Qf)
                  : (mode == 1) ? (z < 3 ? pa.Kr : pa.Kf) : pa.V;
    const int vhalf = (z >= 3) ? 1 : 0;

    #pragma unroll
    for (int hh = 0; hh < 2; hh++) {
        acc_to_sC(sC, acc, tid, hh, 1.f, pa.bias[z], bn);
        __syncthreads();
        const int mbase = bm + hh * 64;
        const int b = mbase >> 10, h0 = bn >> 6;
        if (mode < 2) {
            const int s0 = mbase & 1023;
            for (int e = tid; e < 64 * 64; e += 256) {
                const int rl = e >> 6, p = e & 63, col = p * 2;
                const int hd = col >> 6, d = col & 63;
                const size_t rowIdx = ((size_t)(b * Hn + h0 + hd)) * Sn + s0 + rl;
                dst[rowIdx * 32 + (d >> 1)] =
                    hpair(sC[rl * 132 + col], sC[rl * 132 + col + 1]);
            }
        } else {
            const int sLoc = mbase & 1023;
            for (int e = tid; e < 32 * 128; e += 256) {
                const int col = e & 127, sl = (e >> 7) * 2;
                const int hd = col >> 6, d = col & 63;
                const size_t vrow = ((size_t)(b * Hn + h0 + hd)) * 128 + vhalf * 64 + d;
                dst[vrow * 512 + ((sLoc + sl) >> 1)] =
                    hpair(sC[sl * 132 + col], sC[(sl + 1) * 132 + col]);
            }
        }
        __syncthreads();
    }
}

// ---------------- fused score kernel: both streams, fp16 S (plain) ----------------
__global__ void __launch_bounds__(256, 2) score_kernel(
    const uint32_t* __restrict__ Qr, const uint32_t* __restrict__ Kr,
    const uint32_t* __restrict__ Qf, const uint32_t* __restrict__ Kf,
    uint32_t* __restrict__ Shr, uint32_t* __restrict__ Shf)
{
    extern __shared__ char smem[];
    const uint32_t sb = smem_u32(smem);
    const int tid = threadIdx.x;
    const int z = blockIdx.z;
    const int stream = z >> 6, bh = z & 63;
    const int bm = blockIdx.y * 128, bn = blockIdx.x * 128;

    const uint32_t* A = stream ? Qf : Qr;
    const uint32_t* Bk = stream ? Kf : Kr;
    uint32_t* Sh = (stream ? Shf : Shr) + (size_t)bh * Sn * 512;

    float acc[4][4][4];
    gemm_core<1>(sb, tid, A, nullptr, Bk,
                 ((size_t)bh * Sn + bm) * 32, ((size_t)bh * Sn + bn) * 32, 32, 1, acc);

    float* sC = reinterpret_cast<float*>(smem);
    #pragma unroll
    for (int hh = 0; hh < 2; hh++) {
        acc_to_sC(sC, acc, tid, hh, 0.125f, nullptr, bn);
        __syncthreads();
        const int mbase = bm + hh * 64;
        for (int e = tid; e < 64 * 64; e += 256) {
            const int rl = e >> 6, p = e & 63, col = p * 2;
            Sh[(size_t)(mbase + rl) * 512 + ((bn + col) >> 1)] =
                hpair(sC[rl * 132 + col], sC[rl * 132 + col + 1]);
        }
        __syncthreads();
    }
}

// ---------------- fast exp ----------------
__device__ __forceinline__ float fexp(float x) {
    float t  = x * 1.4426950408889634f;
    float fi = rintf(t);
    float f  = t - fi;
    float p  = 1.3333558146428443e-3f;
    p = fmaf(p, f, 9.6181291076284770e-3f);
    p = fmaf(p, f, 5.5504108664821580e-2f);
    p = fmaf(p, f, 2.4022650695910072e-1f);
    p = fmaf(p, f, 6.9314718055994531e-1f);
    p = fmaf(p, f, 1.0f);
    int e = (int)fi;
    return __int_as_float(__float_as_int(p) + (e << 23));
}

// ---------------- softmax both streams + max merge -> fp16 P (plain) ----------------
__global__ void __launch_bounds__(256) softmax_max_kernel(
    const uint32_t* __restrict__ Shr, const uint32_t* __restrict__ Shf,
    uint32_t* __restrict__ Ph)
{
    __shared__ float sred[8];
    const size_t row = blockIdx.x;
    const int t = threadIdx.x;

    uint2 ur = *reinterpret_cast<const uint2*>(Shr + row * 512 + 2 * t);
    uint2 uf = *reinterpret_cast<const uint2*>(Shf + row * 512 + 2 * t);
    float2 r01 = __half22float2(*reinterpret_cast<__half2*>(&ur.x));
    float2 r23 = __half22float2(*reinterpret_cast<__half2*>(&ur.y));
    float2 f01 = __half22float2(*reinterpret_cast<__half2*>(&uf.x));
    float2 f23 = __half22float2(*reinterpret_cast<__half2*>(&uf.y));
    float4 xr = make_float4(r01.x, r01.y, r23.x, r23.y);
    float4 xf = make_float4(f01.x, f01.y, f23.x, f23.y);

    float m = fmaxf(fmaxf(xr.x, xr.y), fmaxf(xr.z, xr.w));
    #pragma unroll
    for (int o = 16; o; o >>= 1) m = fmaxf(m, __shfl_xor_sync(0xffffffffu, m, o));
    if ((t & 31) == 0) sred[t >> 5] = m;
    __syncthreads();
    m = sred[0];
    #pragma unroll
    for (int i = 1; i < 8; i++) m = fmaxf(m, sred[i]);

    float er0 = fexp(xr.x - m), er1 = fexp(xr.y - m);
    float er2 = fexp(xr.z - m), er3 = fexp(xr.w - m);
    float s = er0 + er1 + er2 + er3;
    #pragma unroll
    for (int o = 16; o; o >>= 1) s += __shfl_xor_sync(0xffffffffu, s, o);
    __syncthreads();
    if ((t & 31) == 0) sred[t >> 5] = s;
    __syncthreads();
    s = sred[0];
    #pragma unroll
    for (int i = 1; i < 8; i++) s += sred[i];
    const float invZr = 1.0f / s;

    float mf = fmaxf(fmaxf(xf.x, xf.y), fmaxf(xf.z, xf.w));
    #pragma unroll
    for (int o = 16; o; o >>= 1) mf = fmaxf(mf, __shfl_xor_sync(0xffffffffu, mf, o));
    __syncthreads();
    if ((t & 31) == 0) sred[t >> 5] = mf;
    __syncthreads();
    mf = sred[0];
    #pragma unroll
    for (int i = 1; i < 8; i++) mf = fmaxf(mf, sred[i]);

    float ef0 = fexp(xf.x - mf), ef1 = fexp(xf.y - mf);
    float ef2 = fexp(xf.z - mf), ef3 = fexp(xf.w - mf);
    float sf = ef0 + ef1 + ef2 + ef3;
    #pragma unroll
    for (int o = 16; o; o >>= 1) sf += __shfl_xor_sync(0xffffffffu, sf, o);
    __syncthreads();
    if ((t & 31) == 0) sred[t >> 5] = sf;
    __syncthreads();
    sf = sred[0];
    #pragma unroll
    for (int i = 1; i < 8; i++) sf += sred[i];
    const float invZf = 1.0f / sf;

    uint2 outp;
    outp.x = hpair(fmaxf(er0 * invZr, ef0 * invZf), fmaxf(er1 * invZr, ef1 * invZf));
    outp.y = hpair(fmaxf(er2 * invZr, ef2 * invZf), fmaxf(er3 * invZr, ef3 * invZf));
    *reinterpret_cast<uint2*>(Ph + row * 512 + 2 * t) = outp;
}

// ---------------- PV kernel: 1-pass, split hi/lo C output ----------------
__global__ void __launch_bounds__(256, 2) pv_kernel(
    const uint32_t* __restrict__ Ph, const uint32_t* __restrict__ V,
    uint32_t* __restrict__ Crh, uint32_t* __restrict__ Crl,
    uint32_t* __restrict__ Cfh, uint32_t* __restrict__ Cfl)
{
    extern __shared__ char smem[];
    const uint32_t sb = smem_u32(smem);
    const int tid = threadIdx.x;
    const int z = blockIdx.z;
    const int bm = blockIdx.y * 128;

    float acc[4][4][4];
    gemm_core<1>(sb, tid, Ph, nullptr, V,
                 ((size_t)z * Sn + bm) * 512, (size_t)z * 128 * 512, 512, 16, acc);

    float* sC = reinterpret_cast<float*>(smem);
    const int b = z >> 3, h = z & 7;
    #pragma unroll
    for (int hh = 0; hh < 2; hh++) {
        acc_to_sC(sC, acc, tid, hh, 1.f, nullptr, 0);
        __syncthreads();
        const int mbase = bm + hh * 64;
        for (int e = tid; e < 64 * 64; e += 256) {
            const int rl = e >> 6, p = e & 63;
            const int str = p >> 5, d = (p & 31) * 2;
            const int col = str * 64 + d;
            const size_t rowIdx = (size_t)b * Sn + mbase + rl;
            split_store_plain(str ? Cfh : Crh, str ? Cfl : Crl,
                              rowIdx * 256 + h * 32 + (d >> 1),
                              sC[rl * 132 + col], sC[rl * 132 + col + 1]);
        }
        __syncthreads();
    }
}

// ---------------- fused output projections (2-pass A) ----------------
__global__ void __launch_bounds__(256, 2) outproj_kernel(
    const uint32_t* __restrict__ Crh, const uint32_t* __restrict__ Crl,
    const uint32_t* __restrict__ Cfh, const uint32_t* __restrict__ Cfl,
    const uint32_t* __restrict__ Wd, const float* __restrict__ b6,
    const float* __restrict__ b7, float* __restrict__ out)
{
    extern __shared__ char smem[];
    const uint32_t sb = smem_u32(smem);
    const int tid = threadIdx.x;
    const int z = blockIdx.z;
    const int bm = blockIdx.y * 128, bn = blockIdx.x * 128;

    const uint32_t* Ahi = z ? Cfh : Crh;
    const uint32_t* Alo = z ? Cfl : Crl;
    const uint32_t* Bw = Wd + (size_t)(6 + z) * DMn * 256;
    const float* bias = z ? b7 : b6;
    float* C = out + (size_t)z * MROWS * DMn;

    float acc[4][4][4];
    gemm_core<2>(sb, tid, Ahi, Alo, Bw,
                 (size_t)bm * 256, (size_t)bn * 256, 256, 8, acc);

    float* sC = reinterpret_cast<float*>(smem);
    #pragma unroll
    for (int hh = 0; hh < 2; hh++) {
        acc_to_sC(sC, acc, tid, hh, 1.f, bias, bn);
        __syncthreads();
        const int mbase = bm + hh * 64;
        for (int e = tid * 4; e < 64 * 128; e += 1024) {
            const int row = e >> 7, col = e & 127;
            float4 v = make_float4(sC[row * 132 + col],     sC[row * 132 + col + 1],
                                   sC[row * 132 + col + 2], sC[row * 132 + col + 3]);
            *reinterpret_cast<float4*>(&C[(size_t)(mbase + row) * DMn + bn + col]) = v;
        }
        __syncthreads();
    }
}

// ---------------- host ----------------
extern "C" void kernel_launch(void* const* d_in, const int* in_sizes, int n_in,
                              void* d_out, int out_size)
{
    const float* x_rgb  = (const float*)d_in[0];
    const float* x_flow = (const float*)d_in[1];
    Ptrs8 wp; const float* bW[8];
    for (int i = 0; i < 8; i++) { wp.p[i] = (const float*)d_in[2 + 2*i]; bW[i] = (const float*)d_in[3 + 2*i]; }
    float* out = (float*)d_out;

    uint32_t *xr,*xf,*Wd,*Qr,*Qf,*Kr,*Kf,*V,*Shr,*Shf,*Ph,*Crh,*Crl,*Cfh,*Cfl;
    cudaGetSymbolAddress((void**)&xr, g_xr);   cudaGetSymbolAddress((void**)&xf, g_xf);
    cudaGetSymbolAddress((void**)&Wd, g_W);
    cudaGetSymbolAddress((void**)&Qr, g_Qr);   cudaGetSymbolAddress((void**)&Qf, g_Qf);
    cudaGetSymbolAddress((void**)&Kr, g_Kr);   cudaGetSymbolAddress((void**)&Kf, g_Kf);
    cudaGetSymbolAddress((void**)&V, g_V);
    cudaGetSymbolAddress((void**)&Shr, g_Shr); cudaGetSymbolAddress((void**)&Shf, g_Shf);
    cudaGetSymbolAddress((void**)&Ph, g_Ph);
    cudaGetSymbolAddress((void**)&Crh, g_Crh); cudaGetSymbolAddress((void**)&Crl, g_Crl);
    cudaGetSymbolAddress((void**)&Cfh, g_Cfh); cudaGetSymbolAddress((void**)&Cfl, g_Cfl);

    cudaFuncSetAttribute((const void*)proj_kernel,    cudaFuncAttributeMaxDynamicSharedMemorySize, SMEM1);
    cudaFuncSetAttribute((const void*)score_kernel,   cudaFuncAttributeMaxDynamicSharedMemorySize, SMEM1);
    cudaFuncSetAttribute((const void*)pv_kernel,      cudaFuncAttributeMaxDynamicSharedMemorySize, SMEM1);
    cudaFuncSetAttribute((const void*)outproj_kernel, cudaFuncAttributeMaxDynamicSharedMemorySize, SMEM2);

    // 0) conversions
    conv_x<<<dim3(MROWS, 1, 2), 256>>>(x_rgb, x_flow, xr, xf);
    conv_w<<<dim3(DMn, 1, 8), 256>>>(wp, Wd);

    // 1) all six projections
    ProjArgs pa;
    pa.xr = xr; pa.xf = xf; pa.Wd = Wd;
    for (int i = 0; i < 6; i++) pa.bias[i] = bW[i];
    pa.Qr = Qr; pa.Kr = Kr; pa.Qf = Qf; pa.Kf = Kf; pa.V = V;
    proj_kernel<<<dim3(DMn / 128, MROWS / 128, 6), 256, SMEM1>>>(pa);

    // 2) both score batches in one launch (fp16 S out)
    score_kernel<<<dim3(Sn / 128, Sn / 128, 128), 256, SMEM1>>>(Qr, Kr, Qf, Kf, Shr, Shf);

    // 3) softmax + max merge -> fp16 P
    softmax_max_kernel<<<Bn * Hn * Sn, 256>>>(Shr, Shf, Ph);

    // 4) PV for both streams
    pv_kernel<<<dim3(1, Sn / 128, Bn * Hn), 256, SMEM1>>>(Ph, V, Crh, Crl, Cfh, Cfl);

    // 5) both output projections
    outproj_kernel<<<dim3(DMn / 128, MROWS / 128, 2), 256, SMEM2>>>(
        Crh, Crl, Cfh, Cfl, Wd, bW[6], bW[7], out);
}

// round 17
// speedup vs baseline: 1.1949x; 1.1866x over previous
#include <cuda_runtime.h>
#include <cuda_fp16.h>
#include <stdint.h>
#include <math.h>

#define Bn 8
#define Hn 8
#define Sn 1024
#define DMn 512
#define DKn 64
#define MROWS (Bn * 1024)   // 8192

// ---------------- scratch (device globals; no runtime allocation) ----------------
__device__ uint32_t g_xr[MROWS * 256], g_xf[MROWS * 256];      // inputs, single fp16 (permuted)
__device__ uint32_t g_W[8][DMn * 256];                         // weights, single fp16 (permuted)
__device__ uint32_t g_Qr[Bn*Hn*Sn*32], g_Qf[Bn*Hn*Sn*32];      // single fp16 (permuted)
__device__ uint32_t g_Kr[Bn*Hn*Sn*32], g_Kf[Bn*Hn*Sn*32];
__device__ uint32_t g_V[Bn*Hn*128*512];                        // single fp16 (permuted) [bh][Vr d0-63|Vf d64-127][s-pairs]
__device__ uint32_t g_Er[(size_t)Bn*Hn*Sn*512];                // exp(scores) fp16, PLAIN layout
__device__ uint32_t g_Ef[(size_t)Bn*Hn*Sn*512];
__device__ float    g_Zp[2 * 64 * 1024 * 8];                   // per-(stream,bh,row,tile) partial sums
__device__ float    g_iZ[2 * 64 * 1024];                       // per-(stream,bh,row) 1/Z
__device__ uint32_t g_Crh[MROWS * 256], g_Crl[MROWS * 256];    // contexts split (permuted)
__device__ uint32_t g_Cfh[MROWS * 256], g_Cfl[MROWS * 256];

#define SMEM1 33792     // 1-pass gemm kernels
#define SMEMS 34816     // score kernel (sC + scrZ)
#define SMEM2 49152     // 2-pass gemm kernels

__device__ __forceinline__ uint32_t smem_u32(const void* p) {
    uint32_t a;
    asm("{ .reg .u64 t; cvta.to.shared.u64 t, %1; cvt.u32.u64 %0, t; }" : "=r"(a) : "l"(p));
    return a;
}

#define CP_ASYNC16(dst, src) \
    asm volatile("cp.async.cg.shared.global [%0], [%1], 16;" :: "r"(dst), "l"(src))
#define CP_COMMIT() asm volatile("cp.async.commit_group;" ::: "memory")
#define CP_WAIT(n)  asm volatile("cp.async.wait_group %0;" :: "n"(n) : "memory")

__device__ __forceinline__ uint32_t hpair(float a, float b) {
    __half2 t = __floats2half2_rn(a, b);
    return *reinterpret_cast<uint32_t*>(&t);
}

// permuted offset within a row for even k, matching SMEM physical tile order
__device__ __forceinline__ size_t perm_off(size_t rowbase32, int k) {
    const int c = k >> 5, t = (k & 31) >> 1;
    const int g = ((t >> 3) << 1) | ((t >> 1) & 1);
    const int s = ((t & 1) << 1) | ((t >> 2) & 1);
    return rowbase32 + c * 16 + g * 4 + s;
}

__device__ __forceinline__ void single_pair_store(
    uint32_t* __restrict__ dst, size_t rowbase32, int k, float v0, float v1)
{
    dst[perm_off(rowbase32, k)] = hpair(v0, v1);
}

__device__ __forceinline__ void split_pair_store(
    uint32_t* __restrict__ hi, uint32_t* __restrict__ lo,
    size_t rowbase32, int k, float v0, float v1)
{
    const size_t off = perm_off(rowbase32, k);
    __half h0 = __float2half_rn(v0), h1 = __float2half_rn(v1);
    hi[off] = hpair(__half2float(h0), __half2float(h1));
    lo[off] = hpair(v0 - __half2float(h0), v1 - __half2float(h1));
}

// ---------------- converters ----------------
__global__ void conv_x(const float* __restrict__ xr, const float* __restrict__ xf,
                       uint32_t* __restrict__ dr, uint32_t* __restrict__ df)
{
    const float* X = blockIdx.z ? xf : xr;
    uint32_t* D = blockIdx.z ? df : dr;
    const size_t i = (size_t)blockIdx.x * 256 + threadIdx.x;
    const size_t row = i >> 8;
    const int k = (int)(i & 255) * 2;
    float2 v = *reinterpret_cast<const float2*>(X + row * 512 + k);
    single_pair_store(D, row * 256, k, v.x, v.y);
}

struct Ptrs8 { const float* p[8]; };
__global__ void conv_w(Ptrs8 wp, uint32_t* __restrict__ Wd)
{
    const int z = blockIdx.z;
    const float* X = wp.p[z];
    uint32_t* D = Wd + (size_t)z * DMn * 256;
    const size_t i = (size_t)blockIdx.x * 256 + threadIdx.x;
    const size_t row = i >> 8;
    const int k = (int)(i & 255) * 2;
    float2 v = *reinterpret_cast<const float2*>(X + row * 512 + k);
    single_pair_store(D, row * 256, k, v.x, v.y);
}

#define MMA(c, a, b) \
    asm volatile( \
        "mma.sync.aligned.m16n8k16.row.col.f32.f16.f16.f32 " \
        "{%0,%1,%2,%3},{%4,%5,%6,%7},{%8,%9},{%0,%1,%2,%3};" \
        : "+f"((c)[0]), "+f"((c)[1]), "+f"((c)[2]), "+f"((c)[3]) \
        : "r"((a)[0]), "r"((a)[1]), "r"((a)[2]), "r"((a)[3]), \
          "r"((b)[0]), "r"((b)[1]))

// ---------------- shared GEMM mainloop (double-buffered cp.async) ----------------
template <int NPASS>
__device__ __forceinline__ void gemm_core(
    char* smem, uint32_t sb, int tid,
    const uint32_t* __restrict__ Ahi, const uint32_t* __restrict__ Alo,
    const uint32_t* __restrict__ Bs,
    size_t aRow0, size_t bRow0, int rowA32, int nc,
    float acc[4][4][4])
{
    constexpr int T_ALOo = 8192;
    constexpr int T_Bo   = (NPASS == 2) ? 16384 : 8192;
    constexpr int STAGEo = (NPASS == 2) ? 24576 : 16384;

    const int w = tid >> 5, lane = tid & 31;
    const int wm = w >> 2, wn = w & 3;
    const int g = lane >> 2, tig = lane & 3;
    const int prr = tid >> 2, pg = tid & 3;

    #pragma unroll
    for (int i = 0; i < 4; i++)
        #pragma unroll
        for (int j = 0; j < 4; j++)
            #pragma unroll
            for (int c = 0; c < 4; c++) acc[i][j][c] = 0.f;

    auto issue = [&](int cc, int st) {
        const uint32_t so = sb + st * STAGEo;
        #pragma unroll
        for (int it = 0; it < 2; it++) {
            const int r = prr + it * 64;
            const uint32_t sw = (uint32_t)(r * 64 + ((pg * 16) ^ ((r & 2) << 4)));
            const size_t srcA = aRow0 + (size_t)r * rowA32 + cc * 16 + pg * 4;
            const size_t srcB = bRow0 + (size_t)r * rowA32 + cc * 16 + pg * 4;
            CP_ASYNC16(so + sw, Ahi + srcA);
            if (NPASS == 2) CP_ASYNC16(so + T_ALOo + sw, Alo + srcA);
            CP_ASYNC16(so + T_Bo + sw, Bs + srcB);
        }
    };

    issue(0, 0);
    CP_COMMIT();

    for (int cc = 0; cc < nc; cc++) {
        if (cc + 1 < nc) { issue(cc + 1, (cc + 1) & 1); CP_COMMIT(); CP_WAIT(1); }
        else             { CP_WAIT(0); }
        __syncthreads();
        const char* sm = smem + (cc & 1) * STAGEo;

        #pragma unroll
        for (int s = 0; s < 2; s++) {
            uint32_t bfr[4][2], Af[4][4];
            #pragma unroll
            for (int j = 0; j < 4; j++) {
                const int rB = wn * 32 + j * 8 + g;
                const uint32_t co = (uint32_t)((s * 32 + tig * 8) ^ ((rB & 2) << 4)) + rB * 64;
                uint2 u = *reinterpret_cast<const uint2*>(sm + T_Bo + co);
                bfr[j][0] = u.x; bfr[j][1] = u.y;
            }
            #pragma unroll
            for (int i = 0; i < 4; i++) {
                const int r0 = wm * 64 + i * 16 + g;
                const uint32_t co = (uint32_t)((s * 32 + tig * 8) ^ ((r0 & 2) << 4));
                uint2 u = *reinterpret_cast<const uint2*>(sm + r0 * 64 + co);
                uint2 v = *reinterpret_cast<const uint2*>(sm + (r0 + 8) * 64 + co);
                Af[i][0] = u.x; Af[i][1] = v.x; Af[i][2] = u.y; Af[i][3] = v.y;
            }
            #pragma unroll
            for (int i = 0; i < 4; i++)
                #pragma unroll
                for (int j = 0; j < 4; j++) MMA(acc[i][j], Af[i], bfr[j]);
            if (NPASS == 2) {
                #pragma unroll
                for (int i = 0; i < 4; i++) {
                    const int r0 = wm * 64 + i * 16 + g;
                    const uint32_t co = (uint32_t)((s * 32 + tig * 8) ^ ((r0 & 2) << 4));
                    uint2 u = *reinterpret_cast<const uint2*>(sm + T_ALOo + r0 * 64 + co);
                    uint2 v = *reinterpret_cast<const uint2*>(sm + T_ALOo + (r0 + 8) * 64 + co);
                    Af[i][0] = u.x; Af[i][1] = v.x; Af[i][2] = u.y; Af[i][3] = v.y;
                }
                #pragma unroll
                for (int i = 0; i < 4; i++)
                    #pragma unroll
                    for (int j = 0; j < 4; j++) MMA(acc[i][j], Af[i], bfr[j]);
            }
        }
        __syncthreads();
    }
}

// stage this warp-group's half of acc into sC [64][132]
__device__ __forceinline__ void acc_to_sC(float* sC, float acc[4][4][4], int tid,
                                          int hh, float alpha, const float* bias, int bn)
{
    const int w = tid >> 5, lane = tid & 31;
    const int wm = w >> 2, wn = w & 3;
    const int g = lane >> 2, tig = lane & 3;
    if (wm == hh) {
        #pragma unroll
        for (int i = 0; i < 4; i++) {
            const int rl = i * 16 + g;
            #pragma unroll
            for (int j = 0; j < 4; j++) {
                const int cl = wn * 32 + j * 8 + 2 * tig;
                float bv0 = 0.f, bv1 = 0.f;
                if (bias) { bv0 = __ldg(bias + bn + cl); bv1 = __ldg(bias + bn + cl + 1); }
                float2 v0 = make_float2(acc[i][j][0] * alpha + bv0,
                                        acc[i][j][1] * alpha + bv1);
                float2 v1 = make_float2(acc[i][j][2] * alpha + bv0,
                                        acc[i][j][3] * alpha + bv1);
                *reinterpret_cast<float2*>(&sC[rl * 132 + cl]) = v0;
                *reinterpret_cast<float2*>(&sC[(rl + 8) * 132 + cl]) = v1;
            }
        }
    }
}

// ---------------- fused 6-projection kernel (1-pass A) ----------------
struct ProjArgs {
    const uint32_t *xr, *xf, *Wd;
    const float* bias[6];
    uint32_t *Qr, *Kr, *Qf, *Kf, *V;
};

__global__ void __launch_bounds__(256, 2) proj_kernel(ProjArgs pa)
{
    extern __shared__ char smem[];
    const uint32_t sb = smem_u32(smem);
    const int tid = threadIdx.x;
    const int z = blockIdx.z;
    const int bm = blockIdx.y * 128, bn = blockIdx.x * 128;

    const uint32_t* A = (z < 3) ? pa.xr : pa.xf;
    const uint32_t* Bw = pa.Wd + (size_t)z * DMn * 256;

    float acc[4][4][4];
    gemm_core<1>(smem, sb, tid, A, nullptr, Bw,
                 (size_t)bm * 256, (size_t)bn * 256, 256, 16, acc);

    float* sC = reinterpret_cast<float*>(smem);
    const int mode = z % 3;
    uint32_t* dst = (mode == 0) ? (z < 3 ? pa.Qr : pa.Qf)
                  : (mode == 1) ? (z < 3 ? pa.Kr : pa.Kf) : pa.V;
    const int vhalf = (z >= 3) ? 1 : 0;

    #pragma unroll
    for (int hh = 0; hh < 2; hh++) {
        acc_to_sC(sC, acc, tid, hh, 1.f, pa.bias[z], bn);
        __syncthreads();
        const int mbase = bm + hh * 64;
        const int b = mbase >> 10, h0 = bn >> 6;
        if (mode < 2) {
            const int s0 = mbase & 1023;
            for (int e = tid; e < 64 * 64; e += 256) {
                const int rl = e >> 6, p = e & 63, col = p * 2;
                const int hd = col >> 6, d = col & 63;
                const size_t rowIdx = ((size_t)(b * Hn + h0 + hd)) * Sn + s0 + rl;
                single_pair_store(dst, rowIdx * 32, d,
                                  sC[rl * 132 + col], sC[rl * 132 + col + 1]);
            }
        } else {
            const int sLoc = mbase & 1023;
            for (int e = tid; e < 32 * 128; e += 256) {
                const int col = e & 127, sl = (e >> 7) * 2;
                const int hd = col >> 6, d = col & 63;
                const size_t vrow = ((size_t)(b * Hn + h0 + hd)) * 128 + vhalf * 64 + d;
                single_pair_store(dst, vrow * 512, sLoc + sl,
                                  sC[sl * 132 + col], sC[(sl + 1) * 132 + col]);
            }
        }
        __syncthreads();
    }
}

// ---------------- fast exp ----------------
__device__ __forceinline__ float fexp(float x) {
    float t  = x * 1.4426950408889634f;
    float fi = rintf(t);
    float f  = t - fi;
    float p  = 1.3333558146428443e-3f;
    p = fmaf(p, f, 9.6181291076284770e-3f);
    p = fmaf(p, f, 5.5504108664821580e-2f);
    p = fmaf(p, f, 2.4022650695910072e-1f);
    p = fmaf(p, f, 6.9314718055994531e-1f);
    p = fmaf(p, f, 1.0f);
    int e = (int)fi;
    return __int_as_float(__float_as_int(p) + (e << 23));
}

// ---------------- score kernel: S -> E = exp(s/8 - 3) (fp16 plain) + row-sum partials ----------------
// No max subtraction: post-scale scores are O(1); offset -3 keeps exp in fp16 range.
__global__ void __launch_bounds__(256, 2) score_kernel(
    const uint32_t* __restrict__ Qr, const uint32_t* __restrict__ Kr,
    const uint32_t* __restrict__ Qf, const uint32_t* __restrict__ Kf,
    uint32_t* __restrict__ Er, uint32_t* __restrict__ Ef,
    float* __restrict__ Zp)
{
    extern __shared__ char smem[];
    const uint32_t sb = smem_u32(smem);
    const int tid = threadIdx.x;
    const int w = tid >> 5, lane = tid & 31;
    const int wm = w >> 2, wn = w & 3;
    const int g = lane >> 2, tig = lane & 3;
    const int z = blockIdx.z;
    const int stream = z >> 6, bh = z & 63;
    const int bm = blockIdx.y * 128, bn = blockIdx.x * 128;

    const uint32_t* A = stream ? Qf : Qr;
    const uint32_t* Bk = stream ? Kf : Kr;
    uint32_t* Eh = (stream ? Ef : Er) + (size_t)bh * Sn * 512;

    float acc[4][4][4];
    gemm_core<1>(smem, sb, tid, A, nullptr, Bk,
                 (size_t)bh * Sn * 32 + (size_t)bm * 32,
                 (size_t)bh * Sn * 32 + (size_t)bn * 32, 32, 2, acc);

    float* sC = reinterpret_cast<float*>(smem);
    float* scrZ = reinterpret_cast<float*>(smem + 33792);   // [64][4]
    #pragma unroll
    for (int hh = 0; hh < 2; hh++) {
        if (wm == hh) {
            float zs[8];
            #pragma unroll
            for (int q2 = 0; q2 < 8; q2++) zs[q2] = 0.f;
            #pragma unroll
            for (int i = 0; i < 4; i++) {
                const int rl = i * 16 + g;
                #pragma unroll
                for (int j = 0; j < 4; j++) {
                    const int cl = wn * 32 + j * 8 + 2 * tig;
                    const float e0 = fexp(acc[i][j][0] * 0.125f - 3.0f);
                    const float e1 = fexp(acc[i][j][1] * 0.125f - 3.0f);
                    const float e2 = fexp(acc[i][j][2] * 0.125f - 3.0f);
                    const float e3 = fexp(acc[i][j][3] * 0.125f - 3.0f);
                    sC[rl * 132 + cl]           = e0;
                    sC[rl * 132 + cl + 1]       = e1;
                    sC[(rl + 8) * 132 + cl]     = e2;
                    sC[(rl + 8) * 132 + cl + 1] = e3;
                    zs[i * 2]     += e0 + e1;
                    zs[i * 2 + 1] += e2 + e3;
                }
            }
            #pragma unroll
            for (int q2 = 0; q2 < 8; q2++) {
                zs[q2] += __shfl_xor_sync(0xffffffffu, zs[q2], 1);
                zs[q2] += __shfl_xor_sync(0xffffffffu, zs[q2], 2);
            }
            if (tig == 0) {
                #pragma unroll
                for (int q2 = 0; q2 < 8; q2++) {
                    const int rl = (q2 >> 1) * 16 + (q2 & 1) * 8 + g;
                    scrZ[rl * 4 + wn] = zs[q2];
                }
            }
        }
        __syncthreads();
        const int mbase = bm + hh * 64;
        for (int e = tid; e < 64 * 64; e += 256) {
            const int rl = e >> 6, p = e & 63, col = p * 2;
            Eh[(size_t)(mbase + rl) * 512 + ((bn + col) >> 1)] =
                hpair(sC[rl * 132 + col], sC[rl * 132 + col + 1]);
        }
        if (tid < 64) {
            const float zz = scrZ[tid * 4] + scrZ[tid * 4 + 1]
                           + scrZ[tid * 4 + 2] + scrZ[tid * 4 + 3];
            Zp[((size_t)(stream * 64 + bh) * 1024 + mbase + tid) * 8 + blockIdx.x] = zz;
        }
        __syncthreads();
    }
}

// ---------------- reduce Z partials -> 1/Z per row ----------------
__global__ void reduce_z(const float* __restrict__ Zp, float* __restrict__ iZ)
{
    const int i = blockIdx.x * 256 + threadIdx.x;   // 131072 rows
    const float* p = Zp + (size_t)i * 8;
    float s = 0.f;
    #pragma unroll
    for (int k = 0; k < 8; k++) s += p[k];
    iZ[i] = 1.0f / s;
}

// ---------------- PV kernel: p = max(Er*iZr, Ef*iZf) on the fly, MMA with V ----------------
__device__ __forceinline__ uint32_t pcomp(uint32_t er, uint32_t ef, float izr, float izf) {
    float2 fr = __half22float2(*reinterpret_cast<__half2*>(&er));
    float2 ff = __half22float2(*reinterpret_cast<__half2*>(&ef));
    return hpair(fmaxf(fr.x * izr, ff.x * izf), fmaxf(fr.y * izr, ff.y * izf));
}

__global__ void __launch_bounds__(256, 2) pv_kernel(
    const uint32_t* __restrict__ Er, const uint32_t* __restrict__ Ef,
    const float* __restrict__ iZ, const uint32_t* __restrict__ V,
    uint32_t* __restrict__ Crh, uint32_t* __restrict__ Crl,
    uint32_t* __restrict__ Cfh, uint32_t* __restrict__ Cfl)
{
    extern __shared__ char smem[];
    const uint32_t sb = smem_u32(smem);
    const int tid = threadIdx.x;
    const int w = tid >> 5, lane = tid & 31;
    const int wm = w >> 2, wn = w & 3;
    const int g = lane >> 2, tig = lane & 3;
    const int z = blockIdx.z;            // bh
    const int bm = blockIdx.y * 128;

    const int prr = tid >> 2, pg = tid & 3;
    const int aSrc = (pg & 1) * 2 + (pg >> 1) * 8;   // base u32 within 16-u32 chunk

    float izr[2], izf[2];
    #pragma unroll
    for (int it = 0; it < 2; it++) {
        const int q = bm + prr + it * 64;
        izr[it] = iZ[(size_t)z * 1024 + q];
        izf[it] = iZ[(size_t)(64 + z) * 1024 + q];
    }
    const uint32_t* ErB = Er + ((size_t)z * Sn + bm) * 512;
    const uint32_t* EfB = Ef + ((size_t)z * Sn + bm) * 512;
    const size_t vBase = (size_t)z * 128 * 512;

    float acc[4][4][4];
    #pragma unroll
    for (int i = 0; i < 4; i++)
        #pragma unroll
        for (int j = 0; j < 4; j++)
            #pragma unroll
            for (int c = 0; c < 4; c++) acc[i][j][c] = 0.f;

    uint2 eR[2][2], eF[2][2];
    auto ldE = [&](int cc) {
        #pragma unroll
        for (int it = 0; it < 2; it++) {
            const size_t rb = (size_t)(prr + it * 64) * 512 + cc * 16 + aSrc;
            eR[it][0] = *reinterpret_cast<const uint2*>(ErB + rb);
            eR[it][1] = *reinterpret_cast<const uint2*>(ErB + rb + 4);
            eF[it][0] = *reinterpret_cast<const uint2*>(EfB + rb);
            eF[it][1] = *reinterpret_cast<const uint2*>(EfB + rb + 4);
        }
    };
    auto issueV = [&](int cc, int st) {
        const uint32_t so = sb + st * 16384 + 8192;
        #pragma unroll
        for (int it = 0; it < 2; it++) {
            const int r = prr + it * 64;
            const uint32_t sw = (uint32_t)(r * 64 + ((pg * 16) ^ ((r & 2) << 4)));
            CP_ASYNC16(so + sw, V + vBase + (size_t)r * 512 + cc * 16 + pg * 4);
        }
    };
    auto stsA = [&](int st) {
        #pragma unroll
        for (int it = 0; it < 2; it++) {
            const int r = prr + it * 64;
            uint4 o;
            o.x = pcomp(eR[it][0].x, eF[it][0].x, izr[it], izf[it]);   // slot a
            o.y = pcomp(eR[it][1].x, eF[it][1].x, izr[it], izf[it]);   // slot a+4
            o.z = pcomp(eR[it][0].y, eF[it][0].y, izr[it], izf[it]);   // slot a+1
            o.w = pcomp(eR[it][1].y, eF[it][1].y, izr[it], izf[it]);   // slot a+5
            const uint32_t sw = (uint32_t)(r * 64 + ((pg * 16) ^ ((r & 2) << 4)));
            *reinterpret_cast<uint4*>(smem + st * 16384 + sw) = o;
        }
    };

    ldE(0);
    issueV(0, 0);
    CP_COMMIT();

    for (int cc = 0; cc < 32; cc++) {
        stsA(cc & 1);
        if (cc + 1 < 32) {
            issueV(cc + 1, (cc + 1) & 1); CP_COMMIT();
            ldE(cc + 1);
            CP_WAIT(1);
        } else CP_WAIT(0);
        __syncthreads();

        const char* sm = smem + (cc & 1) * 16384;
        #pragma unroll
        for (int s = 0; s < 2; s++) {
            uint32_t bfr[4][2], Af[4][4];
            #pragma unroll
            for (int j = 0; j < 4; j++) {
                const int rB = wn * 32 + j * 8 + g;
                const uint32_t co = (uint32_t)((s * 32 + tig * 8) ^ ((rB & 2) << 4)) + rB * 64;
                uint2 u = *reinterpret_cast<const uint2*>(sm + 8192 + co);
                bfr[j][0] = u.x; bfr[j][1] = u.y;
            }
            #pragma unroll
            for (int i = 0; i < 4; i++) {
                const int r0 = wm * 64 + i * 16 + g;
                const uint32_t co = (uint32_t)((s * 32 + tig * 8) ^ ((r0 & 2) << 4));
                uint2 u = *reinterpret_cast<const uint2*>(sm + r0 * 64 + co);
                uint2 v = *reinterpret_cast<const uint2*>(sm + (r0 + 8) * 64 + co);
                Af[i][0] = u.x; Af[i][1] = v.x; Af[i][2] = u.y; Af[i][3] = v.y;
            }
            #pragma unroll
            for (int i = 0; i < 4; i++)
                #pragma unroll
                for (int j = 0; j < 4; j++) MMA(acc[i][j], Af[i], bfr[j]);
        }
        __syncthreads();
    }

    // epilogue: acc -> sC -> split hi/lo contexts (permuted)
    float* sC = reinterpret_cast<float*>(smem);
    const int b = z >> 3, h = z & 7;
    #pragma unroll
    for (int hh = 0; hh < 2; hh++) {
        acc_to_sC(sC, acc, tid, hh, 1.f, nullptr, 0);
        __syncthreads();
        const int mbase = bm + hh * 64;
        for (int e = tid; e < 64 * 64; e += 256) {
            const int rl = e >> 6, p = e & 63;
            const int str = p >> 5, d = (p & 31) * 2;
            const int col = str * 64 + d;
            const size_t rowIdx = (size_t)b * Sn + mbase + rl;
            split_pair_store(str ? Cfh : Crh, str ? Cfl : Crl, rowIdx * 256, h * 64 + d,
                             sC[rl * 132 + col], sC[rl * 132 + col + 1]);
        }
        __syncthreads();
    }
}

// ---------------- fused output projections (2-pass A) ----------------
__global__ void __launch_bounds__(256, 2) outproj_kernel(
    const uint32_t* __restrict__ Crh, const uint32_t* __restrict__ Crl,
    const uint32_t* __restrict__ Cfh, const uint32_t* __restrict__ Cfl,
    const uint32_t* __restrict__ Wd, const float* __restrict__ b6,
    const float* __restrict__ b7, float* __restrict__ out)
{
    extern __shared__ char smem[];
    const uint32_t sb = smem_u32(smem);
    const int tid = threadIdx.x;
    const int z = blockIdx.z;
    const int bm = blockIdx.y * 128, bn = blockIdx.x * 128;

    const uint32_t* Ahi = z ? Cfh : Crh;
    const uint32_t* Alo = z ? Cfl : Crl;
    const uint32_t* Bw = Wd + (size_t)(6 + z) * DMn * 256;
    const float* bias = z ? b7 : b6;
    float* C = out + (size_t)z * MROWS * DMn;

    float acc[4][4][4];
    gemm_core<2>(smem, sb, tid, Ahi, Alo, Bw,
                 (size_t)bm * 256, (size_t)bn * 256, 256, 16, acc);

    float* sC = reinterpret_cast<float*>(smem);
    #pragma unroll
    for (int hh = 0; hh < 2; hh++) {
        acc_to_sC(sC, acc, tid, hh, 1.f, bias, bn);
        __syncthreads();
        const int mbase = bm + hh * 64;
        for (int e = tid * 4; e < 64 * 128; e += 1024) {
            const int row = e >> 7, col = e & 127;
            float4 v = make_float4(sC[row * 132 + col],     sC[row * 132 + col + 1],
                                   sC[row * 132 + col + 2], sC[row * 132 + col + 3]);
            *reinterpret_cast<float4*>(&C[(size_t)(mbase + row) * DMn + bn + col]) = v;
        }
        __syncthreads();
    }
}

// ---------------- host ----------------
extern "C" void kernel_launch(void* const* d_in, const int* in_sizes, int n_in,
                              void* d_out, int out_size)
{
    const float* x_rgb  = (const float*)d_in[0];
    const float* x_flow = (const float*)d_in[1];
    Ptrs8 wp; const float* bW[8];
    for (int i = 0; i < 8; i++) { wp.p[i] = (const float*)d_in[2 + 2*i]; bW[i] = (const float*)d_in[3 + 2*i]; }
    float* out = (float*)d_out;

    uint32_t *xr,*xf,*Wd,*Qr,*Qf,*Kr,*Kf,*V,*Er,*Ef,*Crh,*Crl,*Cfh,*Cfl;
    float *Zp,*iZ;
    cudaGetSymbolAddress((void**)&xr, g_xr);   cudaGetSymbolAddress((void**)&xf, g_xf);
    cudaGetSymbolAddress((void**)&Wd, g_W);
    cudaGetSymbolAddress((void**)&Qr, g_Qr);   cudaGetSymbolAddress((void**)&Qf, g_Qf);
    cudaGetSymbolAddress((void**)&Kr, g_Kr);   cudaGetSymbolAddress((void**)&Kf, g_Kf);
    cudaGetSymbolAddress((void**)&V, g_V);
    cudaGetSymbolAddress((void**)&Er, g_Er);   cudaGetSymbolAddress((void**)&Ef, g_Ef);
    cudaGetSymbolAddress((void**)&Zp, g_Zp);   cudaGetSymbolAddress((void**)&iZ, g_iZ);
    cudaGetSymbolAddress((void**)&Crh, g_Crh); cudaGetSymbolAddress((void**)&Crl, g_Crl);
    cudaGetSymbolAddress((void**)&Cfh, g_Cfh); cudaGetSymbolAddress((void**)&Cfl, g_Cfl);

    cudaFuncSetAttribute((const void*)proj_kernel,    cudaFuncAttributeMaxDynamicSharedMemorySize, SMEM1);
    cudaFuncSetAttribute((const void*)score_kernel,   cudaFuncAttributeMaxDynamicSharedMemorySize, SMEMS);
    cudaFuncSetAttribute((const void*)pv_kernel,      cudaFuncAttributeMaxDynamicSharedMemorySize, SMEM1);
    cudaFuncSetAttribute((const void*)outproj_kernel, cudaFuncAttributeMaxDynamicSharedMemorySize, SMEM2);

    // 0) conversions
    conv_x<<<dim3(MROWS, 1, 2), 256>>>(x_rgb, x_flow, xr, xf);
    conv_w<<<dim3(DMn, 1, 8), 256>>>(wp, Wd);

    // 1) all six projections
    ProjArgs pa;
    pa.xr = xr; pa.xf = xf; pa.Wd = Wd;
    for (int i = 0; i < 6; i++) pa.bias[i] = bW[i];
    pa.Qr = Qr; pa.Kr = Kr; pa.Qf = Qf; pa.Kf = Kf; pa.V = V;
    proj_kernel<<<dim3(DMn / 128, MROWS / 128, 6), 256, SMEM1>>>(pa);

    // 2) scores -> E = exp(s/8 - 3) + per-tile Z partials (both streams, one launch)
    score_kernel<<<dim3(Sn / 128, Sn / 128, 128), 256, SMEMS>>>(Qr, Kr, Qf, Kf, Er, Ef, Zp);

    // 3) reduce Z partials -> 1/Z
    reduce_z<<<512, 256>>>(Zp, iZ);

    // 4) PV with on-the-fly softmax-normalize + max-merge
    pv_kernel<<<dim3(1, Sn / 128, Bn * Hn), 256, SMEM1>>>(Er, Ef, iZ, V, Crh, Crl, Cfh, Cfl);

    // 5) both output projections
    outproj_kernel<<<dim3(DMn / 128, MROWS / 128, 2), 256, SMEM2>>>(
        Crh, Crl, Cfh, Cfl, Wd, bW[6], bW[7], out);
}